// round 7
// baseline (speedup 1.0000x reference)
#include <cuda_runtime.h>
#include <cstdint>

// Persistent single-kernel MLP: x[N,16] -> L1+BN+ReLU -> L2+BN+ReLU -> L3+BN+ReLU -> L4(->1)
// 296 CTAs (co-resident at occ 2), in-kernel grid barriers between layers, in-kernel BN
// stat reduction, cp.async double-buffered tiles, packed f32x2 FFMA GEMM.

#define EPSV 1e-5f
#define NCTA 296
#define TR 128                 // tile rows
#define KP32 33                // smem stride (floats) for 32-wide rows: conflict-free
#define KP16 17                // smem stride for 16-wide rows

__device__ float g_Z[(size_t)2097152 * 32];
__device__ float g_partial[NCTA * 64];
__device__ float g_bnab[64];                       // a[32], c[32]
__device__ unsigned int g_cnt[4]  = {0, 0, 0, 0};  // monotonic across graph replays
__device__ unsigned int g_flag[4] = {0, 0, 0, 0};

// ---------------- packed f32x2 helpers ----------------
__device__ __forceinline__ unsigned long long pack2(float lo, float hi) {
    unsigned long long r;
    asm("mov.b64 %0, {%1, %2};" : "=l"(r) : "r"(__float_as_uint(lo)), "r"(__float_as_uint(hi)));
    return r;
}
__device__ __forceinline__ void unpack2(unsigned long long v, float& lo, float& hi) {
    unsigned int a, b;
    asm("mov.b64 {%0, %1}, %2;" : "=r"(a), "=r"(b) : "l"(v));
    lo = __uint_as_float(a); hi = __uint_as_float(b);
}
__device__ __forceinline__ unsigned long long splat2(float x) {
    unsigned long long r;
    unsigned int xi = __float_as_uint(x);
    asm("mov.b64 %0, {%1, %1};" : "=l"(r) : "r"(xi));
    return r;
}
__device__ __forceinline__ void fma2(unsigned long long& d, unsigned long long a, unsigned long long b) {
    asm("fma.rn.f32x2 %0, %1, %2, %0;" : "+l"(d) : "l"(a), "l"(b));
}
__device__ __forceinline__ void add2(unsigned long long& d, unsigned long long a) {
    asm("add.rn.f32x2 %0, %0, %1;" : "+l"(d) : "l"(a));
}

// ---------------- async copy + sync helpers ----------------
__device__ __forceinline__ unsigned int smem_u32(const void* p) {
    return (unsigned int)__cvta_generic_to_shared(p);
}
__device__ __forceinline__ void cp4(unsigned int dst, const float* src) {
    asm volatile("cp.async.ca.shared.global [%0], [%1], 4;" :: "r"(dst), "l"(src));
}
__device__ __forceinline__ void cp_commit() { asm volatile("cp.async.commit_group;" ::: "memory"); }
__device__ __forceinline__ void cp_wait1()  { asm volatile("cp.async.wait_group 1;" ::: "memory"); }
__device__ __forceinline__ void cp_wait0()  { asm volatile("cp.async.wait_group 0;" ::: "memory"); }
__device__ __forceinline__ unsigned int ld_acq(unsigned int* p) {
    unsigned int v;
    asm volatile("ld.acquire.gpu.u32 %0, [%1];" : "=r"(v) : "l"(p));
    return v;
}
__device__ __forceinline__ void st_rel(unsigned int* p, unsigned int v) {
    asm volatile("st.release.gpu.u32 [%0], %1;" :: "l"(p), "r"(v));
}

struct Smem {
    float T[2][TR * KP32];               // 33792 B, staging + z-transpose scratch
    unsigned long long Wp[32 * 16];      // 4096 B
    unsigned long long Bp[16];
    float A[32], C[32];                  // BN coeffs of current input layer
    unsigned long long Red[8][16];       // warp stat staging
    float Stot[64];                      // cross-CTA reduce scratch / w4 stage
    unsigned int ticket;
};

// ---------------- one layer: z = BNReLU(zin) @ W^T + b, stats of z ----------------
template<int KIN, bool BN>
__device__ void run_layer(Smem& sm, const float* __restrict__ zin,
                          const float* __restrict__ W, const float* __restrict__ b,
                          int ntiles, int tid)
{
    constexpr int KP  = (KIN == 32) ? KP32 : KP16;
    constexpr int PER = TR * KIN / 256;            // floats staged per thread per tile

    // stage weights (packed feature pairs) + bias
    for (int idx = tid; idx < KIN * 16; idx += 256) {
        int k = idx >> 4, jj = idx & 15;
        sm.Wp[idx] = pack2(W[(2 * jj) * KIN + k], W[(2 * jj + 1) * KIN + k]);
    }
    if (tid < 16) sm.Bp[tid] = pack2(b[2 * tid], b[2 * tid + 1]);
    __syncthreads();

    const int half = tid >> 7;         // feature half
    const int r    = tid & 127;        // row slot

    unsigned long long vsum[8], vsq[8];
#pragma unroll
    for (int m = 0; m < 8; ++m) { vsum[m] = 0ull; vsq[m] = 0ull; }

    // prologue: prefetch first tile into buffer 0
    const int t0 = blockIdx.x;
    {
        const float* src = zin + (size_t)t0 * TR * KIN;
        float* dstT = sm.T[0];
#pragma unroll
        for (int j = 0; j < PER; ++j) {
            int i = tid + 256 * j;
            cp4(smem_u32(&dstT[(i / KIN) * KP + (i % KIN)]), src + i);
        }
        cp_commit();
    }

    int it = 0;
    for (int t = t0; t < ntiles; t += NCTA, ++it) {
        const int cur = it & 1;

        // prefetch next tile into the other buffer (fully consumed 1 iteration ago)
        const int tn = t + NCTA;
        if (tn < ntiles) {
            const float* src = zin + (size_t)tn * TR * KIN;
            float* dstT = sm.T[cur ^ 1];
#pragma unroll
            for (int j = 0; j < PER; ++j) {
                int i = tid + 256 * j;
                cp4(smem_u32(&dstT[(i / KIN) * KP + (i % KIN)]), src + i);
            }
        }
        cp_commit();
        cp_wait1();            // current tile complete (next may stay in flight)
        __syncthreads();

        float* T = sm.T[cur];

        // ---- GEMM: 16 features of row r; BN+ReLU applied at read ----
        unsigned long long z0[8];
        const unsigned long long* bp = &sm.Bp[half * 8];
#pragma unroll
        for (int m = 0; m < 8; ++m) z0[m] = bp[m];

#pragma unroll
        for (int k = 0; k < KIN; ++k) {
            float raw = T[r * KP + k];
            float v = BN ? fmaxf(fmaf(raw, sm.A[k], sm.C[k]), 0.0f) : raw;
            unsigned long long p0 = splat2(v);
            const ulonglong2* wp = reinterpret_cast<const ulonglong2*>(&sm.Wp[k * 16 + half * 8]);
            ulonglong2 wa = wp[0], wb = wp[1], wc = wp[2], wd = wp[3];
            fma2(z0[0], p0, wa.x); fma2(z0[1], p0, wa.y);
            fma2(z0[2], p0, wb.x); fma2(z0[3], p0, wb.y);
            fma2(z0[4], p0, wc.x); fma2(z0[5], p0, wc.y);
            fma2(z0[6], p0, wd.x); fma2(z0[7], p0, wd.y);
        }

        // ---- stats ----
#pragma unroll
        for (int m = 0; m < 8; ++m) {
            add2(vsum[m], z0[m]);
            fma2(vsq[m], z0[m], z0[m]);
        }
        __syncthreads();                 // all GEMM reads of T done

        // ---- scatter z into T (stride-33 scratch, conflict-free) ----
#pragma unroll
        for (int m = 0; m < 8; ++m) {
            float f0, f1;
            unpack2(z0[m], f0, f1);
            T[r * KP32 + half * 16 + 2 * m]     = f0;
            T[r * KP32 + half * 16 + 2 * m + 1] = f1;
        }
        __syncthreads();

        // ---- coalesced z store ----
        float4* dst = reinterpret_cast<float4*>(g_Z + (size_t)t * TR * 32);
#pragma unroll
        for (int j = 0; j < 4; ++j) {
            int i = tid + 256 * j;                    // 1024 float4 per tile
            int rw = i >> 3, c = (i & 7) * 4;
            const float* s = &T[rw * KP32 + c];
            float4 v4; v4.x = s[0]; v4.y = s[1]; v4.z = s[2]; v4.w = s[3];
            dst[i] = v4;
        }
        __syncthreads();                 // T free before next-iter cp.async targets it
    }
    cp_wait0();
    __syncthreads();

    // ---- deterministic stat reduction -> per-CTA partials ----
#pragma unroll
    for (int off = 16; off > 0; off >>= 1) {
#pragma unroll
        for (int m = 0; m < 8; ++m) {
            add2(vsum[m], __shfl_xor_sync(0xffffffffu, vsum[m], off));
            add2(vsq[m],  __shfl_xor_sync(0xffffffffu, vsq[m],  off));
        }
    }
    const int w = tid >> 5, lane = tid & 31;
    if (lane == 0) {
#pragma unroll
        for (int m = 0; m < 8; ++m) { sm.Red[w][m] = vsum[m]; sm.Red[w][8 + m] = vsq[m]; }
    }
    __syncthreads();
    if (tid < 64) {
        int s = tid >> 5, j = tid & 31;
        int hh = j >> 4, m = (j & 15) >> 1, hi = j & 1;
        float tot = 0.0f;
        for (int w2 = hh * 4; w2 < hh * 4 + 4; ++w2) {
            float lo, hp; unpack2(sm.Red[w2][s * 8 + m], lo, hp);
            tot += hi ? hp : lo;
        }
        g_partial[blockIdx.x * 64 + tid] = tot;
    }
    __syncthreads();
}

// ---------------- grid barrier + cross-CTA BN coefficient reduction ----------------
__device__ void bn_barrier(Smem& sm, int ph, const float* __restrict__ gamma,
                           const float* __restrict__ beta, float invN, int tid)
{
    __threadfence();                    // publish partials + z stores (all threads)
    __syncthreads();
    if (tid == 0) sm.ticket = atomicAdd(&g_cnt[ph], 1);
    __syncthreads();
    const unsigned int ticket = sm.ticket;
    const unsigned int need = ticket - (ticket % NCTA) + NCTA;   // release value this generation

    if (ticket % NCTA == NCTA - 1) {
        __threadfence();                // acquire side: see all partials
        if (tid < 64) {
            float s0 = 0.f, s1 = 0.f;
            for (int c = 0; c < NCTA - 1; c += 2) {
                s0 += g_partial[c * 64 + tid];
                s1 += g_partial[(c + 1) * 64 + tid];
            }
            sm.Stot[tid] = s0 + s1;     // NCTA even
        }
        __syncthreads();
        if (tid < 32) {
            float mean = sm.Stot[tid] * invN;
            float var  = sm.Stot[32 + tid] * invN - mean * mean;
            float a = gamma[tid] * rsqrtf(var + EPSV);
            g_bnab[tid]      = a;
            g_bnab[32 + tid] = beta[tid] - mean * a;
        }
        __threadfence();
        __syncthreads();
        if (tid == 0) st_rel(&g_flag[ph], need);
    }
    if (tid == 0) {
        while ((int)(ld_acq(&g_flag[ph]) - need) < 0) __nanosleep(128);
    }
    __syncthreads();
    if (tid < 32) { sm.A[tid] = g_bnab[tid]; sm.C[tid] = g_bnab[32 + tid]; }
    __syncthreads();
}

// ---------------- the persistent kernel ----------------
__global__ void __launch_bounds__(256, 2) mlp_kernel(
    const float* __restrict__ x,
    const float* __restrict__ W1, const float* __restrict__ b1,
    const float* __restrict__ g1, const float* __restrict__ be1,
    const float* __restrict__ W2, const float* __restrict__ b2,
    const float* __restrict__ g2, const float* __restrict__ be2,
    const float* __restrict__ W3, const float* __restrict__ b3,
    const float* __restrict__ g3, const float* __restrict__ be3,
    const float* __restrict__ W4, const float* __restrict__ b4,
    float* __restrict__ out, int ntiles, int nrows, float invN)
{
    __shared__ Smem sm;
    const int tid = threadIdx.x;

    // L1: x(16) -> z1
    run_layer<16, false>(sm, x, W1, b1, ntiles, tid);
    bn_barrier(sm, 0, g1, be1, invN, tid);

    // L2: BN1ReLU(z1)(32) -> z2
    run_layer<32, true>(sm, g_Z, W2, b2, ntiles, tid);
    bn_barrier(sm, 1, g2, be2, invN, tid);

    // L3: BN2ReLU(z2)(32) -> z3
    run_layer<32, true>(sm, g_Z, W3, b3, ntiles, tid);
    bn_barrier(sm, 2, g3, be3, invN, tid);

    // L4: BN3ReLU(z3) . w4 + b4
    if (tid < 32) sm.Stot[tid] = W4[tid];
    __syncthreads();
    const float bb = b4[0];
    for (size_t i = (size_t)blockIdx.x * 256 + tid; i < (size_t)nrows; i += (size_t)NCTA * 256) {
        const float4* zr = reinterpret_cast<const float4*>(g_Z + i * 32);
        float acc = bb;
#pragma unroll
        for (int q = 0; q < 8; ++q) {
            float4 v = zr[q];
            int k = q * 4;
            acc = fmaf(fmaxf(fmaf(v.x, sm.A[k + 0], sm.C[k + 0]), 0.0f), sm.Stot[k + 0], acc);
            acc = fmaf(fmaxf(fmaf(v.y, sm.A[k + 1], sm.C[k + 1]), 0.0f), sm.Stot[k + 1], acc);
            acc = fmaf(fmaxf(fmaf(v.z, sm.A[k + 2], sm.C[k + 2]), 0.0f), sm.Stot[k + 2], acc);
            acc = fmaf(fmaxf(fmaf(v.w, sm.A[k + 3], sm.C[k + 3]), 0.0f), sm.Stot[k + 3], acc);
        }
        out[i] = acc;
    }
}

// ---------------- launcher ----------------
extern "C" void kernel_launch(void* const* d_in, const int* in_sizes, int n_in,
                              void* d_out, int out_size)
{
    const float* x   = (const float*)d_in[0];
    const float* W1  = (const float*)d_in[1];
    const float* b1  = (const float*)d_in[2];
    const float* g1  = (const float*)d_in[3];
    const float* be1 = (const float*)d_in[4];
    const float* W2  = (const float*)d_in[5];
    const float* b2  = (const float*)d_in[6];
    const float* g2  = (const float*)d_in[7];
    const float* be2 = (const float*)d_in[8];
    const float* W3  = (const float*)d_in[9];
    const float* b3  = (const float*)d_in[10];
    const float* g3  = (const float*)d_in[11];
    const float* be3 = (const float*)d_in[12];
    const float* W4  = (const float*)d_in[13];
    const float* b4  = (const float*)d_in[14];

    const int n      = in_sizes[0] / 16;        // 2097152 rows
    const int ntiles = n / TR;                  // 16384
    const float invN = 1.0f / (float)n;

    mlp_kernel<<<NCTA, 256>>>(x, W1, b1, g1, be1, W2, b2, g2, be2,
                              W3, b3, g3, be3, W4, b4,
                              (float*)d_out, ntiles, n, invN);
}

// round 9
// speedup vs baseline: 1.1126x; 1.1126x over previous
#include <cuda_runtime.h>
#include <cstdint>

// Persistent single-kernel MLP: x[N,16] -> L1+BN+ReLU -> L2+BN+ReLU -> L3+BN+ReLU -> L4(->1)
// v5: 16B cp.async.cg double-buffered staging with XOR swizzle, float4 activation reads,
// float4 BN at read, packed f32x2 FFMA GEMM, in-kernel grid barriers + BN reduction.

#define EPSV 1e-5f
#define NCTA 296
#define TR 128                  // tile rows
#define TBUF 4224               // floats per tile buffer: max(swizzled 128*32, scratch 128*33)

__device__ float g_Z[(size_t)2097152 * 32];
__device__ float g_partial[NCTA * 64];
__device__ float g_bnab[64];                       // a[32], c[32]
__device__ unsigned int g_cnt[4]  = {0, 0, 0, 0};  // monotonic across graph replays
__device__ unsigned int g_flag[4] = {0, 0, 0, 0};

// ---------------- packed f32x2 helpers ----------------
__device__ __forceinline__ unsigned long long pack2(float lo, float hi) {
    unsigned long long r;
    asm("mov.b64 %0, {%1, %2};" : "=l"(r) : "r"(__float_as_uint(lo)), "r"(__float_as_uint(hi)));
    return r;
}
__device__ __forceinline__ void unpack2(unsigned long long v, float& lo, float& hi) {
    unsigned int a, b;
    asm("mov.b64 {%0, %1}, %2;" : "=r"(a), "=r"(b) : "l"(v));
    lo = __uint_as_float(a); hi = __uint_as_float(b);
}
__device__ __forceinline__ unsigned long long splat2(float x) {
    unsigned long long r;
    unsigned int xi = __float_as_uint(x);
    asm("mov.b64 %0, {%1, %1};" : "=l"(r) : "r"(xi));
    return r;
}
__device__ __forceinline__ void fma2(unsigned long long& d, unsigned long long a, unsigned long long b) {
    asm("fma.rn.f32x2 %0, %1, %2, %0;" : "+l"(d) : "l"(a), "l"(b));
}
__device__ __forceinline__ void add2(unsigned long long& d, unsigned long long a) {
    asm("add.rn.f32x2 %0, %0, %1;" : "+l"(d) : "l"(a));
}

// ---------------- async copy + sync helpers ----------------
__device__ __forceinline__ unsigned int smem_u32(const void* p) {
    return (unsigned int)__cvta_generic_to_shared(p);
}
__device__ __forceinline__ void cp16(unsigned int dst, const float4* src) {
    asm volatile("cp.async.cg.shared.global [%0], [%1], 16;" :: "r"(dst), "l"(src));
}
__device__ __forceinline__ void cp_commit() { asm volatile("cp.async.commit_group;" ::: "memory"); }
__device__ __forceinline__ void cp_wait1()  { asm volatile("cp.async.wait_group 1;" ::: "memory"); }
__device__ __forceinline__ void cp_wait0()  { asm volatile("cp.async.wait_group 0;" ::: "memory"); }
__device__ __forceinline__ unsigned int ld_acq(unsigned int* p) {
    unsigned int v;
    asm volatile("ld.acquire.gpu.u32 %0, [%1];" : "=r"(v) : "l"(p));
    return v;
}
__device__ __forceinline__ void st_rel(unsigned int* p, unsigned int v) {
    asm volatile("st.release.gpu.u32 [%0], %1;" :: "l"(p), "r"(v));
}

struct __align__(16) Smem {
    float T[2][TBUF];                    // staging (swizzled f4) + z scratch (stride 33)
    unsigned long long Wp[32 * 16];      // Wp[k*16+jj] = {W[2jj][k], W[2jj+1][k]}
    unsigned long long Bp[16];
    __align__(16) float A[32];           // BN scale of input layer
    __align__(16) float C[32];           // BN shift
    unsigned long long Red[8][16];
    float Stot[64];
    unsigned int ticket;
};

// swizzled float4 index within a staged tile
template<int KIN>
__device__ __forceinline__ int swz(int row, int c) {
    constexpr int C4 = KIN / 4;
    if (KIN == 32) return row * C4 + (c ^ (row & 7));
    else           return row * C4 + ((c + (row >> 1)) & 3);
}

// ---------------- one layer: z = BNReLU(zin) @ W^T + b, stats of z ----------------
template<int KIN, bool BN>
__device__ void run_layer(Smem& sm, const float* __restrict__ zin,
                          const float* __restrict__ W, const float* __restrict__ b,
                          int ntiles, int tid)
{
    constexpr int C4  = KIN / 4;                 // float4 chunks per row
    constexpr int PER = TR * C4 / 256;           // cp.async.16B per thread per tile

    for (int idx = tid; idx < KIN * 16; idx += 256) {
        int k = idx >> 4, jj = idx & 15;
        sm.Wp[idx] = pack2(W[(2 * jj) * KIN + k], W[(2 * jj + 1) * KIN + k]);
    }
    if (tid < 16) sm.Bp[tid] = pack2(b[2 * tid], b[2 * tid + 1]);
    __syncthreads();

    const int half = tid >> 7;
    const int r    = tid & 127;

    unsigned long long vsum[8], vsq[8];
#pragma unroll
    for (int m = 0; m < 8; ++m) { vsum[m] = 0ull; vsq[m] = 0ull; }

    // prologue: prefetch first tile into buffer 0
    const int t0 = blockIdx.x;
    {
        const float4* src = reinterpret_cast<const float4*>(zin + (size_t)t0 * TR * KIN);
        float* dstT = sm.T[0];
#pragma unroll
        for (int j = 0; j < PER; ++j) {
            int i = tid + 256 * j;
            cp16(smem_u32(dstT + swz<KIN>(i / C4, i % C4) * 4), src + i);
        }
        cp_commit();
    }

    int it = 0;
    for (int t = t0; t < ntiles; t += NCTA, ++it) {
        const int cur = it & 1;

        const int tn = t + NCTA;
        if (tn < ntiles) {
            const float4* src = reinterpret_cast<const float4*>(zin + (size_t)tn * TR * KIN);
            float* dstT = sm.T[cur ^ 1];
#pragma unroll
            for (int j = 0; j < PER; ++j) {
                int i = tid + 256 * j;
                cp16(smem_u32(dstT + swz<KIN>(i / C4, i % C4) * 4), src + i);
            }
        }
        cp_commit();
        cp_wait1();
        __syncthreads();

        float* T = sm.T[cur];
        const float4* T4 = reinterpret_cast<const float4*>(T);

        // ---- GEMM: 16 features of row r ----
        unsigned long long z0[8];
        const unsigned long long* bp = &sm.Bp[half * 8];
#pragma unroll
        for (int m = 0; m < 8; ++m) z0[m] = bp[m];

#pragma unroll
        for (int c = 0; c < C4; ++c) {
            float4 v = T4[swz<KIN>(r, c)];
            if (BN) {
                float4 A4 = reinterpret_cast<const float4*>(sm.A)[c];
                float4 C4v = reinterpret_cast<const float4*>(sm.C)[c];
                v.x = fmaxf(fmaf(v.x, A4.x, C4v.x), 0.0f);
                v.y = fmaxf(fmaf(v.y, A4.y, C4v.y), 0.0f);
                v.z = fmaxf(fmaf(v.z, A4.z, C4v.z), 0.0f);
                v.w = fmaxf(fmaf(v.w, A4.w, C4v.w), 0.0f);
            }
            const float fv[4] = {v.x, v.y, v.z, v.w};
#pragma unroll
            for (int u = 0; u < 4; ++u) {
                int k = c * 4 + u;
                unsigned long long p0 = splat2(fv[u]);
                const ulonglong2* wp = reinterpret_cast<const ulonglong2*>(&sm.Wp[k * 16 + half * 8]);
                ulonglong2 wa = wp[0], wb = wp[1], wc = wp[2], wd = wp[3];
                fma2(z0[0], p0, wa.x); fma2(z0[1], p0, wa.y);
                fma2(z0[2], p0, wb.x); fma2(z0[3], p0, wb.y);
                fma2(z0[4], p0, wc.x); fma2(z0[5], p0, wc.y);
                fma2(z0[6], p0, wd.x); fma2(z0[7], p0, wd.y);
            }
        }

        // ---- stats ----
#pragma unroll
        for (int m = 0; m < 8; ++m) {
            add2(vsum[m], z0[m]);
            fma2(vsq[m], z0[m], z0[m]);
        }
        __syncthreads();                 // all GEMM reads of T done

        // ---- scatter z into T scratch (stride 33, conflict-free) ----
#pragma unroll
        for (int m = 0; m < 8; ++m) {
            float f0, f1;
            unpack2(z0[m], f0, f1);
            T[r * 33 + half * 16 + 2 * m]     = f0;
            T[r * 33 + half * 16 + 2 * m + 1] = f1;
        }
        __syncthreads();

        // ---- coalesced z store ----
        float4* dst = reinterpret_cast<float4*>(g_Z + (size_t)t * TR * 32);
#pragma unroll
        for (int j = 0; j < 4; ++j) {
            int i = tid + 256 * j;
            int rw = i >> 3, col = (i & 7) * 4;
            const float* s = &T[rw * 33 + col];
            float4 v4; v4.x = s[0]; v4.y = s[1]; v4.z = s[2]; v4.w = s[3];
            dst[i] = v4;
        }
        __syncthreads();                 // scratch free before next prefetch cycle
    }
    cp_wait0();
    __syncthreads();

    // ---- deterministic stat reduction -> per-CTA partials ----
#pragma unroll
    for (int off = 16; off > 0; off >>= 1) {
#pragma unroll
        for (int m = 0; m < 8; ++m) {
            add2(vsum[m], __shfl_xor_sync(0xffffffffu, vsum[m], off));
            add2(vsq[m],  __shfl_xor_sync(0xffffffffu, vsq[m],  off));
        }
    }
    const int w = tid >> 5, lane = tid & 31;
    if (lane == 0) {
#pragma unroll
        for (int m = 0; m < 8; ++m) { sm.Red[w][m] = vsum[m]; sm.Red[w][8 + m] = vsq[m]; }
    }
    __syncthreads();
    if (tid < 64) {
        int s = tid >> 5, j = tid & 31;
        int hh = j >> 4, m = (j & 15) >> 1, hi = j & 1;
        float tot = 0.0f;
        for (int w2 = hh * 4; w2 < hh * 4 + 4; ++w2) {
            float lo, hp; unpack2(sm.Red[w2][s * 8 + m], lo, hp);
            tot += hi ? hp : lo;
        }
        g_partial[blockIdx.x * 64 + tid] = tot;
    }
    __syncthreads();
}

// ---------------- grid barrier + cross-CTA BN coefficient reduction ----------------
__device__ void bn_barrier(Smem& sm, int ph, const float* __restrict__ gamma,
                           const float* __restrict__ beta, float invN, int tid)
{
    __threadfence();
    __syncthreads();
    if (tid == 0) sm.ticket = atomicAdd(&g_cnt[ph], 1);
    __syncthreads();
    const unsigned int ticket = sm.ticket;
    const unsigned int need = ticket - (ticket % NCTA) + NCTA;

    if (ticket % NCTA == NCTA - 1) {
        __threadfence();
        if (tid < 64) {
            float s0 = 0.f, s1 = 0.f;
            for (int c = 0; c < NCTA - 1; c += 2) {
                s0 += g_partial[c * 64 + tid];
                s1 += g_partial[(c + 1) * 64 + tid];
            }
            sm.Stot[tid] = s0 + s1;
        }
        __syncthreads();
        if (tid < 32) {
            float mean = sm.Stot[tid] * invN;
            float var  = sm.Stot[32 + tid] * invN - mean * mean;
            float a = gamma[tid] * rsqrtf(var + EPSV);
            g_bnab[tid]      = a;
            g_bnab[32 + tid] = beta[tid] - mean * a;
        }
        __threadfence();
        __syncthreads();
        if (tid == 0) st_rel(&g_flag[ph], need);
    }
    if (tid == 0) {
        while ((int)(ld_acq(&g_flag[ph]) - need) < 0) __nanosleep(128);
    }
    __syncthreads();
    if (tid < 32) { sm.A[tid] = g_bnab[tid]; sm.C[tid] = g_bnab[32 + tid]; }
    __syncthreads();
}

// ---------------- the persistent kernel ----------------
__global__ void __launch_bounds__(256, 2) mlp_kernel(
    const float* __restrict__ x,
    const float* __restrict__ W1, const float* __restrict__ b1,
    const float* __restrict__ g1, const float* __restrict__ be1,
    const float* __restrict__ W2, const float* __restrict__ b2,
    const float* __restrict__ g2, const float* __restrict__ be2,
    const float* __restrict__ W3, const float* __restrict__ b3,
    const float* __restrict__ g3, const float* __restrict__ be3,
    const float* __restrict__ W4, const float* __restrict__ b4,
    float* __restrict__ out, int ntiles, int nrows, float invN)
{
    __shared__ Smem sm;
    const int tid = threadIdx.x;

    run_layer<16, false>(sm, x, W1, b1, ntiles, tid);
    bn_barrier(sm, 0, g1, be1, invN, tid);

    run_layer<32, true>(sm, g_Z, W2, b2, ntiles, tid);
    bn_barrier(sm, 1, g2, be2, invN, tid);

    run_layer<32, true>(sm, g_Z, W3, b3, ntiles, tid);
    bn_barrier(sm, 2, g3, be3, invN, tid);

    // L4: BN3ReLU(z3) . w4 + b4
    if (tid < 32) sm.Stot[tid] = W4[tid];
    __syncthreads();
    const float bb = b4[0];
    for (size_t i = (size_t)blockIdx.x * 256 + tid; i < (size_t)nrows; i += (size_t)NCTA * 256) {
        const float4* zr = reinterpret_cast<const float4*>(g_Z + i * 32);
        float acc = bb;
#pragma unroll
        for (int q = 0; q < 8; ++q) {
            float4 v = zr[q];
            int k = q * 4;
            acc = fmaf(fmaxf(fmaf(v.x, sm.A[k + 0], sm.C[k + 0]), 0.0f), sm.Stot[k + 0], acc);
            acc = fmaf(fmaxf(fmaf(v.y, sm.A[k + 1], sm.C[k + 1]), 0.0f), sm.Stot[k + 1], acc);
            acc = fmaf(fmaxf(fmaf(v.z, sm.A[k + 2], sm.C[k + 2]), 0.0f), sm.Stot[k + 2], acc);
            acc = fmaf(fmaxf(fmaf(v.w, sm.A[k + 3], sm.C[k + 3]), 0.0f), sm.Stot[k + 3], acc);
        }
        out[i] = acc;
    }
}

// ---------------- launcher ----------------
extern "C" void kernel_launch(void* const* d_in, const int* in_sizes, int n_in,
                              void* d_out, int out_size)
{
    const float* x   = (const float*)d_in[0];
    const float* W1  = (const float*)d_in[1];
    const float* b1  = (const float*)d_in[2];
    const float* g1  = (const float*)d_in[3];
    const float* be1 = (const float*)d_in[4];
    const float* W2  = (const float*)d_in[5];
    const float* b2  = (const float*)d_in[6];
    const float* g2  = (const float*)d_in[7];
    const float* be2 = (const float*)d_in[8];
    const float* W3  = (const float*)d_in[9];
    const float* b3  = (const float*)d_in[10];
    const float* g3  = (const float*)d_in[11];
    const float* be3 = (const float*)d_in[12];
    const float* W4  = (const float*)d_in[13];
    const float* b4  = (const float*)d_in[14];

    const int n      = in_sizes[0] / 16;        // 2097152 rows
    const int ntiles = n / TR;                  // 16384
    const float invN = 1.0f / (float)n;

    mlp_kernel<<<NCTA, 256>>>(x, W1, b1, g1, be1, W2, b2, g2, be2,
                              W3, b3, g3, be3, W4, b4,
                              (float*)d_out, ntiles, n, invN);
}